// round 7
// baseline (speedup 1.0000x reference)
#include <cuda_runtime.h>
#include <cstdint>

// FieldAwareFM: B=16384, F=10 fields, D=8.
// y[b] = b_lin + sum_f w[xoff[b,f]] + sum_{f<g} <emb[f, xoff[b,g]], emb[g, xoff[b,f]]>
//
// R3 structure (best): one warp per sample, 2048 blocks x 256, 40 regs.
// Changes vs R3:
//  - packed blocks padded to 384 B = exactly 3 cache lines, 128-aligned
//  - per-task (pair,half) decode via a per-block smem LUT (built once,
//    amortized over the block's 8 samples) instead of per-sample sqrt.

#define BATCH      16384
#define NUM_FIELDS 10
#define FACTOR_DIM 8
#define INPUT_DIM  188610
#define NPAIRS     45
#define NPACKCOLS  8610
#define BLK_F      96          // floats per packed block: 9*8 data + w + pad
#define BLK_B      (BLK_F*4)   // 384 bytes = 3 lines, 128-aligned
#define W_OFF_B    288         // byte offset of folded w inside a block

__constant__ int c_off[NUM_FIELDS] = {
    0, 100000, 150000, 170000, 180000, 185000, 187000, 188000, 188500, 188600
};
__constant__ int c_pb[6] = { 0, 5000, 7000, 8000, 8500, 8600 };  // fields 4..9

__device__ __align__(128) float g_pack[NPACKCOLS * BLK_F];

// ---------------- pack kernel ----------------
__global__ __launch_bounds__(256) void pack_kernel(
    const float* __restrict__ w,
    const float* __restrict__ emb)
{
    int tid = blockIdx.x * blockDim.x + threadIdx.x;   // [0, 8610*20)
    if (tid >= NPACKCOLS * 20) return;
    int jp = tid / 20;
    int u  = tid % 20;
    int c4 = (jp >= 5000) + (jp >= 7000) + (jp >= 8000) + (jp >= 8500) + (jp >= 8600);
    int c  = 4 + c4;
    int col = c_off[c] + (jp - c_pb[c4]);

    if (u < 18) {
        int s = u >> 1, part = u & 1;
        int f = s + (s >= c);
        const float4 v = *reinterpret_cast<const float4*>(
            emb + ((size_t)f * INPUT_DIM + (size_t)col) * FACTOR_DIM + part * 4);
        *reinterpret_cast<float4*>(g_pack + (size_t)jp * BLK_F + s * 8 + part * 4) = v;
    } else if (u == 18) {
        g_pack[(size_t)jp * BLK_F + (W_OFF_B / 4)] = w[col];
    }
}

// ---------------- main kernel ----------------
__global__ __launch_bounds__(256, 6) void ffm_kernel(
    const int*   __restrict__ x,       // (B, 10) int32
    const float* __restrict__ w,       // (INPUT_DIM,)
    const float* __restrict__ blin,    // scalar
    const float* __restrict__ emb,     // (10, INPUT_DIM, 8)
    float*       __restrict__ out)     // (B,)
{
    const unsigned FULL = 0xFFFFFFFFu;

    // Per-task LUT (96 entries), built once per block, used by 8 samples.
    //  .x = f*INPUT_DIM*32  (A raw base, bytes)
    //  .y = g*INPUT_DIM*32  (B raw base, bytes)
    //  .z = f | g<<8 | valid<<16
    //  .w = unused
    __shared__ uint4 lut[96];
    for (int e = threadIdx.x; e < 96; e += blockDim.x) {
        int f = 0, g = 1, vld = 0;
        if (e < 2 * NPAIRS) {
            // pairs sorted g-DESC then f-ASC; exact fp32 sqrt decode
            int   p = e >> 1;
            int   r = NPAIRS - p;
            float s = sqrtf((float)(8 * r + 1));
            g = (int)ceilf((s - 1.0f) * 0.5f);
            f = p - NPAIRS + (g * (g + 1)) / 2;
            vld = 1;
        }
        lut[e] = make_uint4((unsigned)(f * (INPUT_DIM * 32)),
                            (unsigned)(g * (INPUT_DIM * 32)),
                            (unsigned)(f | (g << 8) | (vld << 16)), 0u);
    }
    __syncthreads();

    int b    = (blockIdx.x * blockDim.x + threadIdx.x) >> 5;  // sample id
    int lane = threadIdx.x & 31;
    if (b >= BATCH) return;

    const char* pk = (const char*)g_pack;
    const char* eb = (const char*)emb;

    // Lane f (<10) owns field f. V = byte key:
    //   packed (f>=4): V = ~blockByteBase (negative); raw: V = xoff*32.
    int   V   = 0;
    float acc = 0.0f;
    if (lane < NUM_FIELDS) {
        int xr = x[b * NUM_FIELDS + lane];
        if (lane >= 4) {
            int pbb = (c_pb[lane - 4] + xr) * BLK_B;
            V   = ~pbb;
            acc = *(const float*)(pk + pbb + W_OFF_B);    // w folded into block
        } else {
            V   = (xr + c_off[lane]) * 32;
            acc = w[xr + c_off[lane]];
        }
    }

    const int partB = (lane & 1) << 4;   // 16B half select (t&1 == lane&1)

    float4 va[3], vb[3];
    bool   valid[3];

    #pragma unroll
    for (int k = 0; k < 3; k++) {
        uint4 e = lut[lane + 32 * k];
        int f = e.z & 0xff;
        int g = (e.z >> 8) & 0xff;

        int vg = __shfl_sync(FULL, V, g);   // key of A row: emb[f, x_g]
        int vf = __shfl_sync(FULL, V, f);   // key of B row: emb[g, x_f]

        const char* pA = (vg < 0) ? (pk + (~vg) + f * 32)
                                  : (eb + e.x + (unsigned)vg);
        const char* pB = (vf < 0) ? (pk + (~vf) + (g - 1) * 32)
                                  : (eb + e.y + (unsigned)vf);

        valid[k] = (e.z >> 16) != 0;
        if (valid[k]) {
            va[k] = *(const float4*)(pA + partB);
            vb[k] = *(const float4*)(pB + partB);
        }
    }

    #pragma unroll
    for (int k = 0; k < 3; k++) {
        if (valid[k]) {
            acc += va[k].x * vb[k].x + va[k].y * vb[k].y
                 + va[k].z * vb[k].z + va[k].w * vb[k].w;
        }
    }

    #pragma unroll
    for (int o = 16; o > 0; o >>= 1)
        acc += __shfl_xor_sync(FULL, acc, o);

    if (lane == 0)
        out[b] = acc + blin[0];
}

extern "C" void kernel_launch(void* const* d_in, const int* in_sizes, int n_in,
                              void* d_out, int out_size) {
    const int*   x    = (const int*)  d_in[0];
    const float* w    = (const float*)d_in[1];
    const float* blin = (const float*)d_in[2];
    const float* emb  = (const float*)d_in[3];
    float* out = (float*)d_out;

    const int pack_threads = 256;
    const int pack_blocks  = (NPACKCOLS * 20 + pack_threads - 1) / pack_threads;
    pack_kernel<<<pack_blocks, pack_threads>>>(w, emb);

    const int threads = 256;                      // 8 warps = 8 samples / block
    const int blocks  = (BATCH * 32) / threads;   // 2048
    ffm_kernel<<<blocks, threads>>>(x, w, blin, emb, out);
}

// round 8
// speedup vs baseline: 1.0151x; 1.0151x over previous
#include <cuda_runtime.h>
#include <cstdint>

// FieldAwareFM: B=16384, F=10 fields, D=8.
// y[b] = b_lin + sum_f w[xoff[b,f]] + sum_{f<g} <emb[f, xoff[b,g]], emb[g, xoff[b,f]]>
//
// Structure identical to the best measured kernel (12.32us main):
//   one warp/sample, 2048x256, __launch_bounds__(256,6), per-sample sqrt
//   pair decode, 320B packed blocks.
// Deltas vs that kernel:
//   - packing extended to field 3 (fields 3..9, 18610 cols): per sample,
//     7 of 10 key-blocks now cost 3 lines instead of 9 -> ~53 lines/sample
//   - branchless packed/raw V setup (no BSSY/BSYNC divergence on lanes 0..9)

#define BATCH      16384
#define NUM_FIELDS 10
#define FACTOR_DIM 8
#define INPUT_DIM  188610
#define NPAIRS     45
#define NPACKCOLS  18610       // fields 3..9: 10000+5000+2000+1000+500+100+10
#define BLK_F      80          // floats per packed block (9*8 + w + pad)
#define BLK_B      (BLK_F*4)   // 320 bytes
#define W_OFF_B    288         // byte offset of folded w inside a block

__constant__ int c_off[NUM_FIELDS] = {
    0, 100000, 150000, 170000, 180000, 185000, 187000, 188000, 188500, 188600
};
// pack base per field (fields 3..9; 0..2 unused dummies)
__constant__ int c_pb10[NUM_FIELDS] = {
    0, 0, 0, 0, 10000, 15000, 17000, 18000, 18500, 18600
};

__device__ __align__(128) float g_pack[NPACKCOLS * BLK_F];

// ---------------- pack kernel ----------------
__global__ __launch_bounds__(256) void pack_kernel(
    const float* __restrict__ w,
    const float* __restrict__ emb)
{
    int tid = blockIdx.x * blockDim.x + threadIdx.x;   // [0, 18610*20)
    if (tid >= NPACKCOLS * 20) return;
    int jp = tid / 20;
    int u  = tid % 20;
    int c3 = (jp >= 10000) + (jp >= 15000) + (jp >= 17000)
           + (jp >= 18000) + (jp >= 18500) + (jp >= 18600);
    int c  = 3 + c3;                        // owning field
    int col = c_off[c] + (jp - c_pb10[c]);  // global column index

    if (u < 18) {
        int s = u >> 1, part = u & 1;
        int f = s + (s >= c);               // slot s holds field f (skip c)
        const float4 v = *reinterpret_cast<const float4*>(
            emb + ((size_t)f * INPUT_DIM + (size_t)col) * FACTOR_DIM + part * 4);
        *reinterpret_cast<float4*>(g_pack + (size_t)jp * BLK_F + s * 8 + part * 4) = v;
    } else if (u == 18) {
        g_pack[(size_t)jp * BLK_F + (W_OFF_B / 4)] = w[col];
    }
}

// ---------------- main kernel ----------------
__global__ __launch_bounds__(256, 6) void ffm_kernel(
    const int*   __restrict__ x,       // (B, 10) int32
    const float* __restrict__ w,       // (INPUT_DIM,)
    const float* __restrict__ blin,    // scalar
    const float* __restrict__ emb,     // (10, INPUT_DIM, 8)
    float*       __restrict__ out)     // (B,)
{
    const unsigned FULL = 0xFFFFFFFFu;
    int b    = (blockIdx.x * blockDim.x + threadIdx.x) >> 5;  // sample id
    int lane = threadIdx.x & 31;
    if (b >= BATCH) return;

    const char* pk = (const char*)g_pack;
    const char* eb = (const char*)emb;

    // Lane f (<10) owns field f. V = byte key:
    //   packed (f>=3): V = ~blockByteBase (negative); raw: V = xoff*32.
    // Branchless inside the lane<10 region: pointer select + one LDG.
    int   V   = 0;
    float acc = 0.0f;
    if (lane < NUM_FIELDS) {
        int  xr     = x[b * NUM_FIELDS + lane];
        bool packed = lane >= 3;
        int  pbb    = (c_pb10[lane] + xr) * BLK_B;
        int  rawoff = (xr + c_off[lane]) * 32;
        V = packed ? ~pbb : rawoff;
        const float* ap = packed
            ? (const float*)(pk + pbb + W_OFF_B)          // w folded into block
            : (const float*)((const char*)w + (rawoff >> 3));
        acc = *ap;
    }

    const int partB = (lane & 1) << 4;   // 16B half select (t&1 == lane&1)

    float4 va[3], vb[3];
    bool   valid[3];

    #pragma unroll
    for (int k = 0; k < 3; k++) {
        int  t   = lane + 32 * k;            // task id, 90 valid
        bool vld = t < 2 * NPAIRS;
        int  p   = vld ? (t >> 1) : 0;       // pair id (clamped: shfl convergence)

        // Pairs sorted by g DESC then f ASC; exact fp32 sqrt decode:
        // r = 45 - p; g = ceil((sqrt(8r+1)-1)/2); f = p - 45 + g(g+1)/2.
        int   r = NPAIRS - p;
        float s = sqrtf((float)(8 * r + 1));
        int   g = (int)ceilf((s - 1.0f) * 0.5f);
        int   f = p - NPAIRS + (g * (g + 1)) / 2;

        int vg = __shfl_sync(FULL, V, g);    // key of A row: emb[f, x_g]
        int vf = __shfl_sync(FULL, V, f);    // key of B row: emb[g, x_f]

        const char* pA = (vg < 0)
            ? (pk + (~vg) + f * 32)                               // slot f (f<g)
            : (eb + (unsigned)(f * (INPUT_DIM * 32)) + (unsigned)vg);
        const char* pB = (vf < 0)
            ? (pk + (~vf) + (g - 1) * 32)                         // slot g-1 (g>f)
            : (eb + (unsigned)(g * (INPUT_DIM * 32)) + (unsigned)vf);

        valid[k] = vld;
        if (vld) {
            va[k] = *(const float4*)(pA + partB);
            vb[k] = *(const float4*)(pB + partB);
        }
    }

    #pragma unroll
    for (int k = 0; k < 3; k++) {
        if (valid[k]) {
            acc += va[k].x * vb[k].x + va[k].y * vb[k].y
                 + va[k].z * vb[k].z + va[k].w * vb[k].w;
        }
    }

    #pragma unroll
    for (int o = 16; o > 0; o >>= 1)
        acc += __shfl_xor_sync(FULL, acc, o);

    if (lane == 0)
        out[b] = acc + blin[0];
}

extern "C" void kernel_launch(void* const* d_in, const int* in_sizes, int n_in,
                              void* d_out, int out_size) {
    const int*   x    = (const int*)  d_in[0];
    const float* w    = (const float*)d_in[1];
    const float* blin = (const float*)d_in[2];
    const float* emb  = (const float*)d_in[3];
    float* out = (float*)d_out;

    const int pack_threads = 256;
    const int pack_blocks  = (NPACKCOLS * 20 + pack_threads - 1) / pack_threads;
    pack_kernel<<<pack_blocks, pack_threads>>>(w, emb);

    const int threads = 256;                      // 8 warps = 8 samples / block
    const int blocks  = (BATCH * 32) / threads;   // 2048
    ffm_kernel<<<blocks, threads>>>(x, w, blin, emb, out);
}